// round 17
// baseline (speedup 1.0000x reference)
#include <cuda_runtime.h>
#include <cstdint>
#include <cstddef>

#define BATCH   4096
#define FFI     64
#define DDIM    256
#define PAIRS   2016
#define THREADS 128
#define KC      32                 // K elements per chunk
#define NCH     (DDIM / KC)        // 8
#define NSTAGE  4                  // cp.async ring depth
#define SROW    40                 // padded row stride (words), ==8 mod 32
#define BUF_WORDS (FFI * SROW)     // 2560 words = 10240 B per stage

// Hybrid warp split: warp = (tg, kh). tg splits the 20 upper-triangular
// m16n8 tiles into two sets of 10 with minimal row-group unions; kh splits
// k in halves. B frags alias A raw words (C = A*A^T).
__device__ constexpr int hMI[2][10] = {{0,0,0,0,0,0,0,0,3,3},
                                       {1,1,1,1,1,1,2,2,2,2}};
__device__ constexpr int hNJ[2][10] = {{0,1,2,3,4,5,6,7,6,7},
                                       {2,3,4,5,6,7,4,5,6,7}};
__device__ constexpr unsigned hMASK[2] = {0xFFu, 0xFCu};

__device__ __forceinline__ uint32_t f2tf32(float x) {
    uint32_t r;
    asm("cvt.rna.tf32.f32 %0, %1;" : "=r"(r) : "f"(x));
    return r;
}

__device__ __forceinline__ void mma8(float& d0, float& d1, float& d2, float& d3,
                                     uint32_t a0, uint32_t a1, uint32_t a2, uint32_t a3,
                                     uint32_t b0, uint32_t b1) {
    asm("mma.sync.aligned.m16n8k8.row.col.f32.tf32.tf32.f32 "
        "{%0,%1,%2,%3}, {%4,%5,%6,%7}, {%8,%9}, {%0,%1,%2,%3};"
        : "+f"(d0), "+f"(d1), "+f"(d2), "+f"(d3)
        : "r"(a0), "r"(a1), "r"(a2), "r"(a3), "r"(b0), "r"(b1));
}

__device__ __forceinline__ void cp_async16(uint32_t dst, const void* src) {
    asm volatile("cp.async.cg.shared.global [%0], [%1], 16;"
                 :: "r"(dst), "l"(src) : "memory");
}
__device__ __forceinline__ void cp_commit() {
    asm volatile("cp.async.commit_group;" ::: "memory");
}
__device__ __forceinline__ void cp_wait2() {
    asm volatile("cp.async.wait_group 2;" ::: "memory");
}

// One KC=32 chunk for warp (TG, KH): 2 ks-steps in this warp's k-half.
// Per step, the masked row-groups are loaded once each (conflict-free
// LDS.64 at SROW==8 mod 32), cvt.rna'd to tf32, feed this warp's 10 MMAs.
// Lane k-slots (2q, 2q+1) are a k-permutation applied identically to A and
// B fragments (same words, same mapping) -> k-sum unchanged.
template <int TG, int KH>
__device__ __forceinline__ void chunk_mma(const uint32_t* __restrict__ sb,
                                          int lid, float (&acc)[40]) {
    const int grp = lid >> 2, quad = lid & 3;
    const uint32_t* base = sb + grp * SROW + 2 * quad;
#pragma unroll
    for (int ks = 0; ks < 2; ks++) {
        const int k = KH * 16 + ks * 8;
        uint32_t c[8][2];
#pragma unroll
        for (int g = 0; g < 8; g++) {
            if (hMASK[TG] & (1u << g)) {
                uint2 v = *reinterpret_cast<const uint2*>(base + g * 8 * SROW + k);
                c[g][0] = f2tf32(__uint_as_float(v.x));
                c[g][1] = f2tf32(__uint_as_float(v.y));
            }
        }
#pragma unroll
        for (int t = 0; t < 10; t++) {
            const int a = 2 * hMI[TG][t], bj = hNJ[TG][t];
            mma8(acc[4 * t], acc[4 * t + 1], acc[4 * t + 2], acc[4 * t + 3],
                 c[a][0], c[a + 1][0], c[a][1], c[a + 1][1],
                 c[bj][0], c[bj][1]);
        }
    }
}

__device__ __forceinline__ void stg_pack(float* __restrict__ s_red, int i, int j,
                                         float v, bool need_check) {
    if (!need_check || j > i)
        s_red[i * FFI - (i * (i + 1)) / 2 + j - i - 1] = v;
}

template <int TG>
__device__ __forceinline__ void stage_out(const float (&acc)[40], int lid,
                                          float* __restrict__ s_red) {
    const int grp = lid >> 2, quad = lid & 3;
#pragma unroll
    for (int t = 0; t < 10; t++) {
        const int mi = hMI[TG][t], nj = hNJ[TG][t];
        const bool chk = (nj < 2 * mi + 2);   // tile straddles the diagonal
        const int i0 = mi * 16 + grp, i1 = i0 + 8;
        const int j0 = nj * 8 + 2 * quad, j1 = j0 + 1;
        stg_pack(s_red, i0, j0, acc[4 * t + 0], chk);
        stg_pack(s_red, i0, j1, acc[4 * t + 1], chk);
        stg_pack(s_red, i1, j0, acc[4 * t + 2], chk);
        stg_pack(s_red, i1, j1, acc[4 * t + 3], chk);
    }
}

__global__ void __launch_bounds__(THREADS, 5)
gram_ring_kernel(const float* __restrict__ in, float* __restrict__ out) {
    __shared__ __align__(16) uint32_t sb[NSTAGE][BUF_WORDS];   // 40960 B

    const int tid = threadIdx.x;
    const int wid = tid >> 5, lid = tid & 31;
    const int b = blockIdx.x;

    const float* src = in + (size_t)b * (FFI * DDIM);
    uint32_t s0;
    asm("{ .reg .u64 t; cvta.to.shared.u64 t, %1; cvt.u32.u64 %0, t; }"
        : "=r"(s0) : "l"((const void*)sb));

    // cp.async one KC-chunk into ring stage (c % NSTAGE). Always commits so
    // wait_group accounting stays uniform past the end.
    auto issue = [&](int c) {
        if (c < NCH) {
            const uint32_t dst = s0 + (uint32_t)((c & (NSTAGE - 1)) * BUF_WORDS * 4);
            const float* sc = src + c * KC;
#pragma unroll
            for (int i = 0; i < 4; i++) {
                const int idx = tid + THREADS * i;
                const int r = idx >> 3, c4 = idx & 7;    // row, float4-col
                cp_async16(dst + (uint32_t)((r * SROW + c4 * 4) * 4),
                           sc + (size_t)r * DDIM + c4 * 4);
            }
        }
        cp_commit();
    };

    float acc[40];
#pragma unroll
    for (int i = 0; i < 40; i++) acc[i] = 0.0f;

    issue(0); issue(1); issue(2);
    for (int c = 0; c < NCH; c++) {
        cp_wait2();            // groups pending <= 2 -> chunk c landed
        // ONE barrier: makes chunk c visible to all warps AND proves every
        // warp finished reading stage (c-1)%4 (its compute in iter c-1
        // preceded this barrier) -> stage (c+3)%4 == (c-1)%4 is reusable NOW.
        __syncthreads();
        issue(c + 3);          // in flight during this chunk's MMA phase
        const uint32_t* buf = sb[c & (NSTAGE - 1)];
        switch (wid) {         // wid -> (tg = wid&1, kh = wid>>1)
            case 0:  chunk_mma<0, 0>(buf, lid, acc); break;
            case 1:  chunk_mma<1, 0>(buf, lid, acc); break;
            case 2:  chunk_mma<0, 1>(buf, lid, acc); break;
            default: chunk_mma<1, 1>(buf, lid, acc); break;
        }
    }

    // ---- epilogue: per-k-half triangle-packed staging (16128 B, fits in
    // the dead ring stages), then one coalesced add+store pass ----
    __syncthreads();           // all compute done before overwriting stages
    float* s_red = reinterpret_cast<float*>(sb);       // [2][PAIRS]
    switch (wid) {
        case 0:  stage_out<0>(acc, lid, s_red);         break;
        case 1:  stage_out<1>(acc, lid, s_red);         break;
        case 2:  stage_out<0>(acc, lid, s_red + PAIRS); break;
        default: stage_out<1>(acc, lid, s_red + PAIRS); break;
    }
    __syncthreads();

    float* ob = out + (size_t)b * PAIRS;
#pragma unroll 1
    for (int p = tid; p < PAIRS; p += THREADS)
        ob[p] = s_red[p] + s_red[PAIRS + p];
}

extern "C" void kernel_launch(void* const* d_in, const int* in_sizes, int n_in,
                              void* d_out, int out_size) {
    const float* in = (const float*)d_in[0];
    float* out = (float*)d_out;
    (void)in_sizes; (void)n_in; (void)out_size;
    gram_ring_kernel<<<BATCH, THREADS>>>(in, out);
}